// round 5
// baseline (speedup 1.0000x reference)
#include <cuda_runtime.h>

// QConv2d: new_rho[b] = U2 @ rho[b] @ U2^T, U2 = uc[:,2:4] ⊗ ux ⊗ uy
// Register-resident separable evaluation with packed f32x2 FMA (sm_103a FFMA2).
//
// smem tile A: 128 rows x 136 words. Row r = [64 | 4 pad | 64 | 4 pad].
// P2: per-thread row-half, loaded DIRECTLY from gmem into regs, transformed
//     with f32x2 math, stored to A.
// P3: per-thread column-half (stride-1 lanes, conflict-free), f32x2 transform,
//     written back to the same addresses (no interior barrier).
// P4: fused uc on both sides (f32x2) + coalesced float4 stores.

#define NT 256
#define RS 136
#define HO 68
#define A_WORDS (128 * RS)           // 17408
#define SMEM_WORDS (A_WORDS + 128 + 8)
#define SMEM_BYTES (SMEM_WORDS * 4)

typedef unsigned long long u64;

__device__ __forceinline__ u64 f2pack(float lo, float hi) {
    u64 r; asm("mov.b64 %0, {%1, %2};" : "=l"(r) : "f"(lo), "f"(hi)); return r;
}
__device__ __forceinline__ u64 f2dup(float x) { return f2pack(x, x); }
__device__ __forceinline__ void f2unpack(u64 v, float& lo, float& hi) {
    asm("mov.b64 {%0, %1}, %2;" : "=f"(lo), "=f"(hi) : "l"(v));
}
__device__ __forceinline__ u64 f2fma(u64 a, u64 b, u64 c) {
    u64 r; asm("fma.rn.f32x2 %0, %1, %2, %3;" : "=l"(r) : "l"(a), "l"(b), "l"(c));
    return r;
}
__device__ __forceinline__ u64 f2mul(u64 a, u64 b) {
    u64 r; asm("mul.rn.f32x2 %0, %1, %2;" : "=l"(r) : "l"(a), "l"(b)); return r;
}

// In-place 8x8 (x) ⊗ 8x8 (y) transform of a 64-float vector, f32x2 packed.
// Uy/Ux: smem arrays of 32 f32x2, layout [p][k] = {U[2p][k], U[2p+1][k]}.
__device__ __forceinline__ void transform64p(float* __restrict__ d,
                                             const u64* __restrict__ Uy,
                                             const u64* __restrict__ Ux)
{
    // uy pass: contiguous groups (x fixed), contract over y
#pragma unroll
    for (int x = 0; x < 8; x++) {
        u64 acc0, acc1, acc2, acc3;
        {
            const u64 vd = f2dup(d[x * 8]);
            acc0 = f2mul(Uy[0], vd);
            acc1 = f2mul(Uy[8], vd);
            acc2 = f2mul(Uy[16], vd);
            acc3 = f2mul(Uy[24], vd);
        }
#pragma unroll
        for (int k = 1; k < 8; k++) {
            const u64 vd = f2dup(d[x * 8 + k]);
            acc0 = f2fma(Uy[k],      vd, acc0);
            acc1 = f2fma(Uy[8 + k],  vd, acc1);
            acc2 = f2fma(Uy[16 + k], vd, acc2);
            acc3 = f2fma(Uy[24 + k], vd, acc3);
        }
        f2unpack(acc0, d[x * 8 + 0], d[x * 8 + 1]);
        f2unpack(acc1, d[x * 8 + 2], d[x * 8 + 3]);
        f2unpack(acc2, d[x * 8 + 4], d[x * 8 + 5]);
        f2unpack(acc3, d[x * 8 + 6], d[x * 8 + 7]);
    }
    // ux pass: stride-8 groups (y fixed), contract over x
#pragma unroll
    for (int y = 0; y < 8; y++) {
        u64 acc0, acc1, acc2, acc3;
        {
            const u64 vd = f2dup(d[y]);
            acc0 = f2mul(Ux[0], vd);
            acc1 = f2mul(Ux[8], vd);
            acc2 = f2mul(Ux[16], vd);
            acc3 = f2mul(Ux[24], vd);
        }
#pragma unroll
        for (int k = 1; k < 8; k++) {
            const u64 vd = f2dup(d[k * 8 + y]);
            acc0 = f2fma(Ux[k],      vd, acc0);
            acc1 = f2fma(Ux[8 + k],  vd, acc1);
            acc2 = f2fma(Ux[16 + k], vd, acc2);
            acc3 = f2fma(Ux[24 + k], vd, acc3);
        }
        f2unpack(acc0, d[0 * 8 + y], d[1 * 8 + y]);
        f2unpack(acc1, d[2 * 8 + y], d[3 * 8 + y]);
        f2unpack(acc2, d[4 * 8 + y], d[5 * 8 + y]);
        f2unpack(acc3, d[6 * 8 + y], d[7 * 8 + y]);
    }
}

__global__ __launch_bounds__(NT, 2)
void qconv_kernel(const float* __restrict__ rho,
                  const float* __restrict__ gux,
                  const float* __restrict__ guy,
                  const float* __restrict__ guc,
                  float* __restrict__ out)
{
    extern __shared__ float sm[];
    float* A   = sm;                         // 128 x 136 (HO-padded)
    u64*   sUp = (u64*)(sm + A_WORDS);       // [0:32) uy pairs, [32:64) ux pairs
    float* swc = sm + A_WORDS + 128;         // 8 floats: wc[c'*2+c] = uc[c', c+2]

    const int tid = threadIdx.x;
    const int b   = blockIdx.x;

    // ---- init packed U + wc ----
    if (tid < 64) {
        const int m = tid >> 5;              // 0 = uy, 1 = ux
        const int j = tid & 31;
        const int p = j >> 3, k = j & 7;
        const float* src = m ? gux : guy;
        sUp[tid] = f2pack(src[(2 * p) * 8 + k], src[(2 * p + 1) * 8 + k]);
    } else if (tid < 72) {
        const int i = tid - 64;              // i = c'*2 + c
        swc[i] = guc[(i >> 1) * 4 + (i & 1) + 2];
    }

    // ---- P2 loads: row-half straight from gmem into registers ----
    const int r = tid >> 1, h = tid & 1;
    float d[64];
    {
        const float4* src = (const float4*)(rho + (long)b * 16384 + r * 128 + h * 64);
#pragma unroll
        for (int i = 0; i < 16; i++) {
            const float4 v = src[i];
            d[4 * i] = v.x; d[4 * i + 1] = v.y; d[4 * i + 2] = v.z; d[4 * i + 3] = v.w;
        }
    }
    __syncthreads();   // sUp/swc visible

    const u64* Uy = sUp;
    const u64* Ux = sUp + 32;

    // ---- P2: right-side transform + store to smem ----
    transform64p(d, Uy, Ux);
    {
        float* base = A + r * RS + h * HO;
#pragma unroll
        for (int i = 0; i < 16; i++)
            *(float4*)(base + 4 * i) =
                make_float4(d[4 * i], d[4 * i + 1], d[4 * i + 2], d[4 * i + 3]);
    }
    __syncthreads();

    // ---- P3: left-side transform (column-half per thread, stride-1 lanes) ----
    {
        const int cl = tid >> 7;
        const int c  = tid & 127;
        const int off = cl * 64 * RS + (c >> 6) * HO + (c & 63);
#pragma unroll
        for (int i = 0; i < 64; i++) d[i] = A[off + i * RS];
        transform64p(d, Uy, Ux);
#pragma unroll
        for (int i = 0; i < 64; i++) A[off + i * RS] = d[i];
    }
    __syncthreads();

    // ---- P4: fused channel expansion (f32x2) + coalesced store ----
    u64 wd[8];
#pragma unroll
    for (int i = 0; i < 8; i++) wd[i] = f2dup(swc[i]);

    float4* outb = (float4*)(out + (long)b * 65536);
    const float4* Af = (const float4*)A;     // row stride 34 float4; 2nd half at +17

#pragma unroll
    for (int it = 0; it < 4; it++) {
        const int item = tid + it * NT;
        const int irv = item & 15;
        const int il  = item >> 4;

        const float4 m00 = Af[il * 34 + irv];
        const float4 m01 = Af[il * 34 + 17 + irv];
        const float4 m10 = Af[(64 + il) * 34 + irv];
        const float4 m11 = Af[(64 + il) * 34 + 17 + irv];

        const u64 m00a = f2pack(m00.x, m00.y), m00b = f2pack(m00.z, m00.w);
        const u64 m01a = f2pack(m01.x, m01.y), m01b = f2pack(m01.z, m01.w);
        const u64 m10a = f2pack(m10.x, m10.y), m10b = f2pack(m10.z, m10.w);
        const u64 m11a = f2pack(m11.x, m11.y), m11b = f2pack(m11.z, m11.w);

#pragma unroll
        for (int cpr = 0; cpr < 4; cpr++) {
            const u64 w0 = wd[cpr * 2], w1 = wd[cpr * 2 + 1];
            const u64 t0a = f2fma(w1, m01a, f2mul(w0, m00a));
            const u64 t0b = f2fma(w1, m01b, f2mul(w0, m00b));
            const u64 t1a = f2fma(w1, m11a, f2mul(w0, m10a));
            const u64 t1b = f2fma(w1, m11b, f2mul(w0, m10b));
#pragma unroll
            for (int cpl = 0; cpl < 4; cpl++) {
                const u64 v0 = wd[cpl * 2], v1 = wd[cpl * 2 + 1];
                const u64 oa = f2fma(v1, t1a, f2mul(v0, t0a));
                const u64 ob = f2fma(v1, t1b, f2mul(v0, t0b));
                float4 o;
                f2unpack(oa, o.x, o.y);
                f2unpack(ob, o.z, o.w);
                outb[(cpl * 64 + il) * 64 + cpr * 16 + irv] = o;
            }
        }
    }
}

extern "C" void kernel_launch(void* const* d_in, const int* in_sizes, int n_in,
                              void* d_out, int out_size)
{
    const float* rho = (const float*)d_in[0];
    const float* ux  = (const float*)d_in[1];
    const float* uy  = (const float*)d_in[2];
    const float* uc  = (const float*)d_in[3];
    float* out = (float*)d_out;

    const int B = in_sizes[0] / 16384;

    cudaFuncSetAttribute(qconv_kernel,
                         cudaFuncAttributeMaxDynamicSharedMemorySize, SMEM_BYTES);
    qconv_kernel<<<B, NT, SMEM_BYTES>>>(rho, ux, uy, uc, out);
}